// round 10
// baseline (speedup 1.0000x reference)
#include <cuda_runtime.h>
#include <cuda_fp16.h>
#include <cstdint>

// PatchMerged fused: Haar-DWT2 + LayerNorm + (384->192) GEMM, fp16 mma.sync.
// Persistent 512-thread CTAs (16 warps, 4Mx4N grid), weight-resident SMEM,
// M-tile = 128 pixels, ldmatrix fragment loads.
// out[b, l, d] = r*(G - mu*s[d]) + t[d],  G = patch @ W4
//   mu = sum_c x[b,c,2h,2w]/192 ; var = sum_patch x^2/384 - mu^2  (Haar identities)

__device__ __align__(16) __half g_Wh[73728];   // 6 chunks x [192 n-rows x 64 k] swizzled
__device__ float2 g_st2[192];                  // (s,t) folded reduction vectors
__device__ int g_tilectr;

// ---- prep: fold Haar + LN-gamma into W4, emit swizzled fp16 chunk images ----
__global__ void pm_prep_w(const float* __restrict__ nw, const float* __restrict__ wr) {
    int idx = blockIdx.x * 256 + threadIdx.x;
    if (idx >= 384 * 192) return;
    int kg = idx / 192, d = idx - kg * 192;
    int c = kg >> 2, q = kg & 3, dy = q >> 1, dx = q & 1;
    float wll = nw[c]       * wr[c * 192 + d];
    float wlh = nw[96 + c]  * wr[(96 + c) * 192 + d];
    float whl = nw[192 + c] * wr[(192 + c) * 192 + d];
    float whh = nw[288 + c] * wr[(288 + c) * 192 + d];
    float v = 0.5f * (wll + (dy ? -wlh : wlh) + (dx ? -whl : whl)
                          + ((dx ^ dy) ? -whh : whh));
    int ck = c >> 4, kl = ((c & 15) << 2) | q;       // chunk 0..5, k-local 0..63
    int off = ck * 24576 + d * 128 + ((((kl >> 3) ^ (d & 7)) << 4)) + (kl & 7) * 2;
    g_Wh[off >> 1] = __float2half_rn(v);
}

// grid 192 x 128 threads: block = one output channel d; also resets tile counter
__global__ void pm_prep_st(const float* __restrict__ nw, const float* __restrict__ nb,
                           const float* __restrict__ wr) {
    __shared__ float rs[4], rt[4];
    const int d = blockIdx.x, tid = threadIdx.x;
    float s = 0.f, t = 0.f;
    for (int yc = tid; yc < 384; yc += 128) {
        float w = wr[yc * 192 + d];
        s += nw[yc] * w; t += nb[yc] * w;
    }
    #pragma unroll
    for (int o = 16; o > 0; o >>= 1) {
        s += __shfl_down_sync(0xffffffffu, s, o);
        t += __shfl_down_sync(0xffffffffu, t, o);
    }
    if ((tid & 31) == 0) { rs[tid >> 5] = s; rt[tid >> 5] = t; }
    __syncthreads();
    if (tid == 0) {
        g_st2[d] = make_float2(rs[0] + rs[1] + rs[2] + rs[3],
                               rt[0] + rt[1] + rt[2] + rt[3]);
        if (d == 0) g_tilectr = 0;
    }
}

__device__ __forceinline__ uint32_t smem_u32(const void* p) {
    uint32_t a;
    asm("{ .reg .u64 t; cvta.to.shared.u64 t, %1; cvt.u32.u64 %0, t; }" : "=r"(a) : "l"(p));
    return a;
}

// SMEM map (dynamic, 180352 B): W | A double-buffer (stats overlay) | ctr
static constexpr int SM_W   = 0;         // 147456
static constexpr int SM_A   = 147456;    // 2 x 16384 (128 rows x 64 k fp16, swizzled)
static constexpr int SM_RED = 147456;    // overlays A buf0: 16x128 sums | 16x128 ssq
static constexpr int SM_MU  = 163840;    // overlays A buf1 (dead after final MMA)
static constexpr int SM_RR  = 164352;
static constexpr int SM_CTR = 180224;
static constexpr int SMEM_SZ = 180352;

// per-chunk x load: warp wid owns channel ck*16+wid; lanes x j cover 128 pixels
#define LDGX(ck) do {                                                                  \
    _Pragma("unroll") for (int dy = 0; dy < 2; dy++)                                   \
    _Pragma("unroll") for (int j = 0; j < 4; j++)                                      \
        pf[dy][j] = *(const float2*)(x +                                               \
            (((size_t)b * 96 + (ck) * 16 + wid) * 256 + 2 * h + dy) * 256              \
            + 2 * (lane + 32 * j));                                                    \
} while (0)

__global__ void __launch_bounds__(512, 1)
pm_main(const float* __restrict__ x, float* __restrict__ out) {
    extern __shared__ char smem[];
    const uint32_t sb = smem_u32(smem);
    const int tid = threadIdx.x, lane = tid & 31, wid = tid >> 5;
    const int gid = lane >> 2, t4 = lane & 3;
    const int wh = wid >> 2, cp = wid & 3;    // MMA warp grid: 4 (M) x 4 (N)
    const int l7 = lane & 7;

    // ldmatrix per-lane row-offset bases (tile select via lane bits 3,4)
    //   A tiles: (r,k0),(r+8,k0),(r,k8),(r+8,k8):  +8 rows on bit3, +k8 on bit4
    //   B tiles: (n,k0),(n,k8),(n+8,k0),(n+8,k8):  +k8 on bit3, +8 rows on bit4
    const uint32_t arow_off = (uint32_t)((wh * 32 + l7 + ((lane >> 3) & 1) * 8) * 128);
    const uint32_t brow_off = (uint32_t)((cp * 48 + l7 + (lane >> 4) * 8) * 128);
    const int ga_sel = lane >> 4;          // A k-granule bit
    const int gb_sel = (lane >> 3) & 1;    // B k-granule bit

    // A STS address: channel wid -> k-granule wid>>1, byte half (wid&1)*8
    const int ag = wid >> 1, ah8 = (wid & 1) * 8;

    // ---- stage full weight matrix into SMEM (once per CTA) ----
    {
        unsigned long long g0 =
            (unsigned long long)__cvta_generic_to_global((const char*)g_Wh + tid * 16);
        #pragma unroll
        for (int i = 0; i < 18; i++)
            asm volatile("cp.async.cg.shared.global [%0], [%1], 16;"
                         :: "r"(sb + SM_W + tid * 16 + i * 8192),
                            "l"(g0 + (unsigned long long)i * 8192) : "memory");
        asm volatile("cp.async.commit_group;" ::: "memory");
        asm volatile("cp.async.wait_group 0;" ::: "memory");
    }
    __syncthreads();

    float2 pf[2][4];

    for (;;) {
        // ---- steal a tile ----
        if (tid == 0) *(int*)(smem + SM_CTR) = atomicAdd(&g_tilectr, 1);
        __syncthreads();
        const int t = *(int*)(smem + SM_CTR);
        if (t >= 2048) break;
        const int b = t >> 7, h = t & 127;

        float acc[2][6][4];
        #pragma unroll
        for (int i = 0; i < 2; i++)
        #pragma unroll
        for (int j = 0; j < 6; j++)
        #pragma unroll
        for (int q = 0; q < 4; q++) acc[i][j][q] = 0.f;
        float ssum_t[4] = {0, 0, 0, 0}, ssq_t[4] = {0, 0, 0, 0};

        LDGX(0);

        #pragma unroll 1
        for (int ck = 0; ck < 6; ++ck) {
            const uint32_t abuf = sb + SM_A + (uint32_t)((ck & 1) << 14);
            // ---- A: stats (raw f32) + fp16 convert + swizzled STS.64 ----
            #pragma unroll
            for (int j = 0; j < 4; j++) {
                const int p = lane + 32 * j;
                float2 v0 = pf[0][j], v1 = pf[1][j];
                ssum_t[j] += v0.x;
                ssq_t[j]  += v0.x * v0.x + v0.y * v0.y + v1.x * v1.x + v1.y * v1.y;
                __half2 h0 = __floats2half2_rn(v0.x, v0.y);
                __half2 h1 = __floats2half2_rn(v1.x, v1.y);
                asm volatile("st.shared.v2.b32 [%0], {%1,%2};"
                             :: "r"(abuf + p * 128 + ((ag ^ (p & 7)) << 4) + ah8),
                                "r"(*(uint32_t*)&h0), "r"(*(uint32_t*)&h1) : "memory");
            }
            __syncthreads();                 // A(ck) visible; also fences buffer reuse
            if (ck < 5) LDGX(ck + 1);        // DRAM latency hides under MMAs below

            const uint32_t wck = sb + SM_W + (uint32_t)(ck * 24576);
            #pragma unroll
            for (int s = 0; s < 4; s++) {
                uint32_t ua[2][4], ub[6][2];
                const uint32_t xa = (uint32_t)((((2 * s + ga_sel) ^ l7)) << 4);
                const uint32_t xb = (uint32_t)((((2 * s + gb_sel) ^ l7)) << 4);
                #pragma unroll
                for (int mt = 0; mt < 2; mt++)
                    asm volatile(
                        "ldmatrix.sync.aligned.m8n8.x4.shared.b16 {%0,%1,%2,%3}, [%4];"
                        : "=r"(ua[mt][0]), "=r"(ua[mt][1]),
                          "=r"(ua[mt][2]), "=r"(ua[mt][3])
                        : "r"(abuf + arow_off + mt * 2048 + xa));
                #pragma unroll
                for (int p = 0; p < 3; p++)
                    asm volatile(
                        "ldmatrix.sync.aligned.m8n8.x4.shared.b16 {%0,%1,%2,%3}, [%4];"
                        : "=r"(ub[2 * p][0]), "=r"(ub[2 * p][1]),
                          "=r"(ub[2 * p + 1][0]), "=r"(ub[2 * p + 1][1])
                        : "r"(wck + brow_off + p * 2048 + xb));
                #pragma unroll
                for (int mt = 0; mt < 2; mt++)
                #pragma unroll
                for (int nt = 0; nt < 6; nt++)
                    asm volatile(
                        "mma.sync.aligned.m16n8k16.row.col.f32.f16.f16.f32 "
                        "{%0,%1,%2,%3}, {%4,%5,%6,%7}, {%8,%9}, {%0,%1,%2,%3};"
                        : "+f"(acc[mt][nt][0]), "+f"(acc[mt][nt][1]),
                          "+f"(acc[mt][nt][2]), "+f"(acc[mt][nt][3])
                        : "r"(ua[mt][0]), "r"(ua[mt][1]), "r"(ua[mt][2]), "r"(ua[mt][3]),
                          "r"(ub[nt][0]), "r"(ub[nt][1]));
            }
        }

        // ---- LN stats: 16 per-channel partials per pixel -> mu, 1/sigma ----
        // partials overlay A buf0 (last MMAs read buf1); mu/rr overlay buf1 after sync
        #pragma unroll
        for (int j = 0; j < 4; j++) {
            int p = lane + 32 * j;
            *(float*)(smem + SM_RED + (wid * 128 + p) * 4)        = ssum_t[j];
            *(float*)(smem + SM_RED + 8192 + (wid * 128 + p) * 4) = ssq_t[j];
        }
        __syncthreads();
        if (tid < 128) {
            float s = 0.f, qq = 0.f;
            #pragma unroll
            for (int w = 0; w < 16; w++) {
                s  += *(float*)(smem + SM_RED + (w * 128 + tid) * 4);
                qq += *(float*)(smem + SM_RED + 8192 + (w * 128 + tid) * 4);
            }
            float mu = s * (1.f / 192.f);
            float var = qq * (1.f / 384.f) - mu * mu;
            *(float*)(smem + SM_MU + tid * 4) = mu;
            *(float*)(smem + SM_RR + tid * 4) = rsqrtf(var + 1e-5f);
        }
        __syncthreads();

        // ---- fused epilogue from register accumulators ----
        float* ob = out + ((size_t)b * 16384 + (size_t)h * 128) * 192;
        #pragma unroll
        for (int mt = 0; mt < 2; mt++) {
            int row0 = wh * 32 + mt * 16 + gid;
            float mu0 = *(float*)(smem + SM_MU + row0 * 4);
            float r0  = *(float*)(smem + SM_RR + row0 * 4);
            float mu1 = *(float*)(smem + SM_MU + (row0 + 8) * 4);
            float r1  = *(float*)(smem + SM_RR + (row0 + 8) * 4);
            #pragma unroll
            for (int nt = 0; nt < 6; nt++) {
                int cb = cp * 48 + nt * 8 + 2 * t4;
                float2 st0 = __ldg(&g_st2[cb]);
                float2 st1 = __ldg(&g_st2[cb + 1]);
                float2 v0, v1;
                v0.x = r0 * (acc[mt][nt][0] - mu0 * st0.x) + st0.y;
                v0.y = r0 * (acc[mt][nt][1] - mu0 * st1.x) + st1.y;
                v1.x = r1 * (acc[mt][nt][2] - mu1 * st0.x) + st0.y;
                v1.y = r1 * (acc[mt][nt][3] - mu1 * st1.x) + st1.y;
                *(float2*)(ob + (size_t)row0 * 192 + cb)       = v0;
                *(float2*)(ob + (size_t)(row0 + 8) * 192 + cb) = v1;
            }
        }
    }
}

extern "C" void kernel_launch(void* const* d_in, const int* in_sizes, int n_in,
                              void* d_out, int out_size) {
    const float* x  = (const float*)d_in[0];
    const float* nw = (const float*)d_in[1];
    const float* nb = (const float*)d_in[2];
    const float* wr = (const float*)d_in[3];
    float* out = (float*)d_out;
    (void)in_sizes; (void)n_in; (void)out_size;

    static int cfg = 0;
    if (!cfg) {
        cudaFuncSetAttribute(pm_main, cudaFuncAttributeMaxDynamicSharedMemorySize, SMEM_SZ);
        cfg = 1;
    }
    pm_prep_w<<<288, 256>>>(nw, wr);
    pm_prep_st<<<192, 128>>>(nw, nb, wr);
    pm_main<<<148, 512, SMEM_SZ>>>(x, out);
}

// round 11
// speedup vs baseline: 1.1514x; 1.1514x over previous
#include <cuda_runtime.h>
#include <cuda_fp16.h>
#include <cstdint>

// PatchMerged fused: Haar-DWT2 + LayerNorm + (384->192) GEMM, fp16 mma.sync.
// Persistent 256-thread CTAs, weight-resident SMEM, M-tile = 128 pixels,
// ldmatrix fragments, single-sync double-buffered mainloop, cross-tile prefetch.
// out[b, l, d] = r*(G - mu*s[d]) + t[d],  G = patch @ W4
//   mu = sum_c x[b,c,2h,2w]/192 ; var = sum_patch x^2/384 - mu^2  (Haar identities)

__device__ __align__(16) __half g_Wh[73728];   // 6 chunks x [192 n-rows x 64 k] swizzled
__device__ float2 g_st2[192];                  // (s,t) folded reduction vectors
__device__ int g_tilectr;

// ---- prep: fold Haar + LN-gamma into W4, emit swizzled fp16 chunk images ----
__global__ void pm_prep_w(const float* __restrict__ nw, const float* __restrict__ wr) {
    int idx = blockIdx.x * 256 + threadIdx.x;
    if (idx >= 384 * 192) return;
    int kg = idx / 192, d = idx - kg * 192;
    int c = kg >> 2, q = kg & 3, dy = q >> 1, dx = q & 1;
    float wll = nw[c]       * wr[c * 192 + d];
    float wlh = nw[96 + c]  * wr[(96 + c) * 192 + d];
    float whl = nw[192 + c] * wr[(192 + c) * 192 + d];
    float whh = nw[288 + c] * wr[(288 + c) * 192 + d];
    float v = 0.5f * (wll + (dy ? -wlh : wlh) + (dx ? -whl : whl)
                          + ((dx ^ dy) ? -whh : whh));
    int ck = c >> 4, kl = ((c & 15) << 2) | q;       // chunk 0..5, k-local 0..63
    int off = ck * 24576 + d * 128 + ((((kl >> 3) ^ (d & 7)) << 4)) + (kl & 7) * 2;
    g_Wh[off >> 1] = __float2half_rn(v);
}

// grid 192 x 128 threads: block = one output channel d; also resets tile counter
__global__ void pm_prep_st(const float* __restrict__ nw, const float* __restrict__ nb,
                           const float* __restrict__ wr) {
    __shared__ float rs[4], rt[4];
    const int d = blockIdx.x, tid = threadIdx.x;
    float s = 0.f, t = 0.f;
    for (int yc = tid; yc < 384; yc += 128) {
        float w = wr[yc * 192 + d];
        s += nw[yc] * w; t += nb[yc] * w;
    }
    #pragma unroll
    for (int o = 16; o > 0; o >>= 1) {
        s += __shfl_down_sync(0xffffffffu, s, o);
        t += __shfl_down_sync(0xffffffffu, t, o);
    }
    if ((tid & 31) == 0) { rs[tid >> 5] = s; rt[tid >> 5] = t; }
    __syncthreads();
    if (tid == 0) {
        g_st2[d] = make_float2(rs[0] + rs[1] + rs[2] + rs[3],
                               rt[0] + rt[1] + rt[2] + rt[3]);
        if (d == 0) g_tilectr = 0;
    }
}

__device__ __forceinline__ uint32_t smem_u32(const void* p) {
    uint32_t a;
    asm("{ .reg .u64 t; cvta.to.shared.u64 t, %1; cvt.u32.u64 %0, t; }" : "=r"(a) : "l"(p));
    return a;
}

// SMEM map (dynamic, 189568 B): W | A double-buffer | red | mu | rr | ctr
static constexpr int SM_W   = 0;         // 147456
static constexpr int SM_A   = 147456;    // 2 x 16384 (128 rows x 64 k fp16, swizzled)
static constexpr int SM_RED = 180224;    // 8x128 sums, then 8x128 ssq (8192 B)
static constexpr int SM_MU  = 188416;    // 128 f32
static constexpr int SM_RR  = 188928;    // 128 f32
static constexpr int SM_CTR = 189440;
static constexpr int SMEM_SZ = 189568;

// per-chunk x load: warp wid owns channels {16ck+2wid, +1}; lanes x j cover 128 pixels
#define LDGX(bb, hh, ck) do {                                                          \
    _Pragma("unroll") for (int ci = 0; ci < 2; ci++)                                   \
    _Pragma("unroll") for (int dy = 0; dy < 2; dy++)                                   \
    _Pragma("unroll") for (int j = 0; j < 4; j++)                                      \
        pf[ci][dy][j] = *(const float2*)(x +                                           \
            (((size_t)(bb) * 96 + (ck) * 16 + 2 * wid + ci) * 256                      \
             + 2 * (hh) + dy) * 256 + 2 * (lane + 32 * j));                            \
} while (0)

__global__ void __launch_bounds__(256, 1)
pm_main(const float* __restrict__ x, float* __restrict__ out) {
    extern __shared__ char smem[];
    const uint32_t sb = smem_u32(smem);
    const int tid = threadIdx.x, lane = tid & 31, wid = tid >> 5;
    const int gid = lane >> 2, t4 = lane & 3;
    const int wh = wid >> 2, cp = wid & 3;    // MMA warp grid: 2 (M) x 4 (N)
    const int l7 = lane & 7;

    // ldmatrix per-lane row-offset bases (tile select via lane bits 3,4)
    const uint32_t arow_off = (uint32_t)((wh * 64 + l7 + ((lane >> 3) & 1) * 8) * 128);
    const uint32_t brow_off = (uint32_t)((cp * 48 + l7 + (lane >> 4) * 8) * 128);
    const int ga_sel = lane >> 4;          // A k-granule bit
    const int gb_sel = (lane >> 3) & 1;    // B k-granule bit

    // ---- stage full weight matrix into SMEM (once per CTA) ----
    {
        unsigned long long g0 =
            (unsigned long long)__cvta_generic_to_global((const char*)g_Wh + tid * 16);
        #pragma unroll
        for (int i = 0; i < 36; i++)
            asm volatile("cp.async.cg.shared.global [%0], [%1], 16;"
                         :: "r"(sb + SM_W + tid * 16 + i * 4096),
                            "l"(g0 + (unsigned long long)i * 4096) : "memory");
        asm volatile("cp.async.commit_group;" ::: "memory");
        asm volatile("cp.async.wait_group 0;" ::: "memory");
    }

    float2 pf[2][2][4];

    // ---- first tile + its chunk-0 loads ----
    if (tid == 0) *(int*)(smem + SM_CTR) = atomicAdd(&g_tilectr, 1);
    __syncthreads();
    int t = *(int*)(smem + SM_CTR);
    if (t < 2048) LDGX(t >> 7, t & 127, 0);

    while (t < 2048) {
        const int b = t >> 7, h = t & 127;

        float acc[4][6][4];
        #pragma unroll
        for (int i = 0; i < 4; i++)
        #pragma unroll
        for (int j = 0; j < 6; j++)
        #pragma unroll
        for (int q = 0; q < 4; q++) acc[i][j][q] = 0.f;
        float ssum_t[4] = {0, 0, 0, 0}, ssq_t[4] = {0, 0, 0, 0};
        int tn = 2048;

        #pragma unroll 1
        for (int ck = 0; ck < 6; ++ck) {
            const uint32_t abuf = sb + SM_A + (uint32_t)((ck & 1) << 14);
            // ---- A: stats (raw f32) + fp16 convert + swizzled STS.128 ----
            // (safe without a pre-sync: every warp's MMA(ck-2) ldmatrix reads of
            //  this buffer were issued before it arrived at sync(ck-1))
            #pragma unroll
            for (int j = 0; j < 4; j++) {
                const int p = lane + 32 * j;
                float2 v00 = pf[0][0][j], v01 = pf[0][1][j];
                float2 v10 = pf[1][0][j], v11 = pf[1][1][j];
                ssum_t[j] += v00.x + v10.x;
                ssq_t[j]  += v00.x * v00.x + v00.y * v00.y + v01.x * v01.x + v01.y * v01.y
                           + v10.x * v10.x + v10.y * v10.y + v11.x * v11.x + v11.y * v11.y;
                __half2 h0 = __floats2half2_rn(v00.x, v00.y);
                __half2 h1 = __floats2half2_rn(v01.x, v01.y);
                __half2 h2 = __floats2half2_rn(v10.x, v10.y);
                __half2 h3 = __floats2half2_rn(v11.x, v11.y);
                asm volatile("st.shared.v4.b32 [%0], {%1,%2,%3,%4};"
                             :: "r"(abuf + p * 128 + ((wid ^ (p & 7)) << 4)),
                                "r"(*(uint32_t*)&h0), "r"(*(uint32_t*)&h1),
                                "r"(*(uint32_t*)&h2), "r"(*(uint32_t*)&h3) : "memory");
            }
            // ---- next loads BEFORE the barrier (latency hides under MMA+sync) ----
            if (ck == 4 && tid == 0)
                *(int*)(smem + SM_CTR) = atomicAdd(&g_tilectr, 1);   // published by sync(4)
            if (ck < 5) {
                LDGX(b, h, ck + 1);
            } else {
                tn = *(int*)(smem + SM_CTR);
                if (tn < 2048) LDGX(tn >> 7, tn & 127, 0);   // next tile's chunk 0
            }
            __syncthreads();                 // A(ck) visible to all warps
            // ---- MMA on chunk ck ----
            const uint32_t wck = sb + SM_W + (uint32_t)(ck * 24576);
            #pragma unroll
            for (int s = 0; s < 4; s++) {
                uint32_t ua[4][4], ub[6][2];
                const uint32_t xa = (uint32_t)((((2 * s + ga_sel) ^ l7)) << 4);
                const uint32_t xb = (uint32_t)((((2 * s + gb_sel) ^ l7)) << 4);
                #pragma unroll
                for (int mt = 0; mt < 4; mt++)
                    asm volatile(
                        "ldmatrix.sync.aligned.m8n8.x4.shared.b16 {%0,%1,%2,%3}, [%4];"
                        : "=r"(ua[mt][0]), "=r"(ua[mt][1]),
                          "=r"(ua[mt][2]), "=r"(ua[mt][3])
                        : "r"(abuf + arow_off + mt * 2048 + xa));
                #pragma unroll
                for (int p = 0; p < 3; p++)
                    asm volatile(
                        "ldmatrix.sync.aligned.m8n8.x4.shared.b16 {%0,%1,%2,%3}, [%4];"
                        : "=r"(ub[2 * p][0]), "=r"(ub[2 * p][1]),
                          "=r"(ub[2 * p + 1][0]), "=r"(ub[2 * p + 1][1])
                        : "r"(wck + brow_off + p * 2048 + xb));
                #pragma unroll
                for (int mt = 0; mt < 4; mt++)
                #pragma unroll
                for (int nt = 0; nt < 6; nt++)
                    asm volatile(
                        "mma.sync.aligned.m16n8k16.row.col.f32.f16.f16.f32 "
                        "{%0,%1,%2,%3}, {%4,%5,%6,%7}, {%8,%9}, {%0,%1,%2,%3};"
                        : "+f"(acc[mt][nt][0]), "+f"(acc[mt][nt][1]),
                          "+f"(acc[mt][nt][2]), "+f"(acc[mt][nt][3])
                        : "r"(ua[mt][0]), "r"(ua[mt][1]), "r"(ua[mt][2]), "r"(ua[mt][3]),
                          "r"(ub[nt][0]), "r"(ub[nt][1]));
            }
        }

        // ---- LN stats: per-(warp,pixel) partials -> mu, 1/sigma ----
        // (next tile's chunk-0 LDGs are in flight during this whole phase)
        #pragma unroll
        for (int j = 0; j < 4; j++) {
            int p = lane + 32 * j;
            *(float*)(smem + SM_RED + (wid * 128 + p) * 4)        = ssum_t[j];
            *(float*)(smem + SM_RED + 4096 + (wid * 128 + p) * 4) = ssq_t[j];
        }
        __syncthreads();
        if (tid < 128) {
            float s = 0.f, qq = 0.f;
            #pragma unroll
            for (int w = 0; w < 8; w++) {
                s  += *(float*)(smem + SM_RED + (w * 128 + tid) * 4);
                qq += *(float*)(smem + SM_RED + 4096 + (w * 128 + tid) * 4);
            }
            float mu = s * (1.f / 192.f);
            float var = qq * (1.f / 384.f) - mu * mu;
            *(float*)(smem + SM_MU + tid * 4) = mu;
            *(float*)(smem + SM_RR + tid * 4) = rsqrtf(var + 1e-5f);
        }
        __syncthreads();

        // ---- fused epilogue from register accumulators ----
        float* ob = out + ((size_t)b * 16384 + (size_t)h * 128) * 192;
        #pragma unroll
        for (int mt = 0; mt < 4; mt++) {
            int row0 = wh * 64 + mt * 16 + gid;
            float mu0 = *(float*)(smem + SM_MU + row0 * 4);
            float r0  = *(float*)(smem + SM_RR + row0 * 4);
            float mu1 = *(float*)(smem + SM_MU + (row0 + 8) * 4);
            float r1  = *(float*)(smem + SM_RR + (row0 + 8) * 4);
            #pragma unroll
            for (int nt = 0; nt < 6; nt++) {
                int cb = cp * 48 + nt * 8 + 2 * t4;
                float2 st0 = __ldg(&g_st2[cb]);
                float2 st1 = __ldg(&g_st2[cb + 1]);
                float2 v0, v1;
                v0.x = r0 * (acc[mt][nt][0] - mu0 * st0.x) + st0.y;
                v0.y = r0 * (acc[mt][nt][1] - mu0 * st1.x) + st1.y;
                v1.x = r1 * (acc[mt][nt][2] - mu1 * st0.x) + st0.y;
                v1.y = r1 * (acc[mt][nt][3] - mu1 * st1.x) + st1.y;
                *(float2*)(ob + (size_t)row0 * 192 + cb)       = v0;
                *(float2*)(ob + (size_t)(row0 + 8) * 192 + cb) = v1;
            }
        }
        t = tn;
    }
}

extern "C" void kernel_launch(void* const* d_in, const int* in_sizes, int n_in,
                              void* d_out, int out_size) {
    const float* x  = (const float*)d_in[0];
    const float* nw = (const float*)d_in[1];
    const float* nb = (const float*)d_in[2];
    const float* wr = (const float*)d_in[3];
    float* out = (float*)d_out;
    (void)in_sizes; (void)n_in; (void)out_size;

    static int cfg = 0;
    if (!cfg) {
        cudaFuncSetAttribute(pm_main, cudaFuncAttributeMaxDynamicSharedMemorySize, SMEM_SZ);
        cfg = 1;
    }
    pm_prep_w<<<288, 256>>>(nw, wr);
    pm_prep_st<<<192, 128>>>(nw, nb, wr);
    pm_main<<<148, 256, SMEM_SZ>>>(x, out);
}